// round 4
// baseline (speedup 1.0000x reference)
#include <cuda_runtime.h>
#include <cuda_bf16.h>
#include <cstdint>

// Shapes fixed by dataset: q/k (4,16,4096,64) f32, cos/sin (4,4096,64) f32, vs (32,64) f32
#define DD 64
#define SSS 4096
#define NROWS_Q (4*16*4096)    // 262144
#define NROWS_T (2*NROWS_Q)    // 524288
#define NREFL 32

// mma-ready packed bf16 B fragments, uint4 = {hi0, hi1, lo0, lo1}
// GEMM1: B1[k=j][n=i] = Q[i][j]   (Y = X * Q^T)
// GEMM2: B2[k=i][n=j] = Q[i][j]   (O = Z * Q)
__device__ uint4 g_B1[1024];
__device__ uint4 g_B2[1024];

// ---------------- Kernel A: build Q (Householder scan) + pack mma fragments ----------------
__global__ void build_q_kernel(const float* __restrict__ vs) {
    __shared__ float Qs[DD*DD];
    __shared__ float vsh[DD];
    __shared__ float wpart[4][DD];
    __shared__ float coefs[NREFL];
    const int t = threadIdx.x;          // 256 threads
    const int j = t & 63;
    const int p = t >> 6;

    for (int i = p*16; i < p*16 + 16; ++i)
        Qs[i*DD + j] = (i == j) ? 1.0f : 0.0f;

    if (t < NREFL) {
        float s = 0.0f;
        for (int c = 0; c < DD; ++c) { float v = vs[t*DD + c]; s += v*v; }
        coefs[t] = 2.0f / (s + 1e-8f);
    }
    __syncthreads();

    for (int r = 0; r < NREFL; ++r) {
        if (t < DD) vsh[t] = vs[r*DD + t];
        __syncthreads();
        float w = 0.0f;
        #pragma unroll
        for (int i = 0; i < 16; ++i) {
            int ii = p*16 + i;
            w += vsh[ii] * Qs[ii*DD + j];
        }
        wpart[p][j] = w;
        __syncthreads();
        float wj = wpart[0][j] + wpart[1][j] + wpart[2][j] + wpart[3][j];
        float cw = coefs[r] * wj;
        #pragma unroll
        for (int i = 0; i < 16; ++i) {
            int ii = p*16 + i;
            Qs[ii*DD + j] -= vsh[ii] * cw;
        }
        __syncthreads();
    }

    // pack B fragments (hi/lo bf16 split, uint4) for both GEMMs
    for (int slot = t; slot < 1024; slot += 256) {
        int lane = slot & 31, frag = slot >> 5;
        int kt = frag >> 3, nt = frag & 7;
        int g = lane >> 2, t4 = lane & 3;
        int n  = 8*nt + g;
        int k0 = 16*kt + 2*t4;

        // ---- B1 (element at (k,n) = Q[n][k]) ----
        {
            float e0 = Qs[n*DD + k0],     e1 = Qs[n*DD + k0 + 1];
            float e2 = Qs[n*DD + k0 + 8], e3 = Qs[n*DD + k0 + 9];
            __nv_bfloat162 h0 = __floats2bfloat162_rn(e0, e1);
            __nv_bfloat162 h1 = __floats2bfloat162_rn(e2, e3);
            float r0 = e0 - __bfloat162float(h0.x), r1 = e1 - __bfloat162float(h0.y);
            float r2 = e2 - __bfloat162float(h1.x), r3 = e3 - __bfloat162float(h1.y);
            __nv_bfloat162 l0 = __floats2bfloat162_rn(r0, r1);
            __nv_bfloat162 l1 = __floats2bfloat162_rn(r2, r3);
            g_B1[slot] = make_uint4(*(uint32_t*)&h0, *(uint32_t*)&h1,
                                    *(uint32_t*)&l0, *(uint32_t*)&l1);
        }
        // ---- B2 (element at (k,n) = Q[k][n]) ----
        {
            float e0 = Qs[k0*DD + n],     e1 = Qs[(k0+1)*DD + n];
            float e2 = Qs[(k0+8)*DD + n], e3 = Qs[(k0+9)*DD + n];
            __nv_bfloat162 h0 = __floats2bfloat162_rn(e0, e1);
            __nv_bfloat162 h1 = __floats2bfloat162_rn(e2, e3);
            float r0 = e0 - __bfloat162float(h0.x), r1 = e1 - __bfloat162float(h0.y);
            float r2 = e2 - __bfloat162float(h1.x), r3 = e3 - __bfloat162float(h1.y);
            __nv_bfloat162 l0 = __floats2bfloat162_rn(r0, r1);
            __nv_bfloat162 l1 = __floats2bfloat162_rn(r2, r3);
            g_B2[slot] = make_uint4(*(uint32_t*)&h0, *(uint32_t*)&h1,
                                    *(uint32_t*)&l0, *(uint32_t*)&l1);
        }
    }
}

// ---------------- helpers ----------------
__device__ __forceinline__ uint32_t pk_bf16x2(float lo, float hi) {
    uint32_t d;
    asm("cvt.rn.bf16x2.f32 %0, %1, %2;" : "=r"(d) : "f"(hi), "f"(lo));
    return d;
}
__device__ __forceinline__ void split_bf16x2(float a, float b, uint32_t& hi, uint32_t& lo) {
    hi = pk_bf16x2(a, b);
    float ha = __uint_as_float(hi << 16);
    float hb = __uint_as_float(hi & 0xFFFF0000u);
    lo = pk_bf16x2(a - ha, b - hb);
}

#define MMA_BF16(c, a0, a1, a2, a3, b0, b1)                                        \
    asm volatile("mma.sync.aligned.m16n8k16.row.col.f32.bf16.bf16.f32 "            \
                 "{%0,%1,%2,%3}, {%4,%5,%6,%7}, {%8,%9}, {%0,%1,%2,%3};"           \
                 : "+f"(c[0]), "+f"(c[1]), "+f"(c[2]), "+f"(c[3])                   \
                 : "r"(a0), "r"(a1), "r"(a2), "r"(a3), "r"(b0), "r"(b1))

// ---------------- Kernel B ----------------
// Block = 256 threads (8 warps). Block covers ONE (tensor, b, s-chunk of 8) across ALL 16 heads:
// 128 rows, local row rl = h*8 + ds. Each warp handles ONE 16-row M-tile (2 heads).
// cos/sin tile is 8 rows, shared by all heads and both fragment row-halves.
#define XS_STRIDE 68
__global__ void __launch_bounds__(256, 2) rnrope_mma_kernel(
    const float* __restrict__ qin, const float* __restrict__ kin,
    const float* __restrict__ cosp, const float* __restrict__ sinp,
    float* __restrict__ out)
{
    __shared__ float xs[128 * XS_STRIDE];   // x tile; reused for out tile
    __shared__ float cs[8 * XS_STRIDE];
    __shared__ float ss[8 * XS_STRIDE];

    const int tid  = threadIdx.x;
    const int warp = tid >> 5;
    const int lane = tid & 31;
    const int g    = lane >> 2;
    const int t4   = lane & 3;

    const int bid    = blockIdx.x;          // 4096 blocks
    const int tensor = bid >> 11;           // 0 = q, 1 = k
    const int b      = (bid >> 9) & 3;
    const int s0     = (bid & 511) << 3;
    const float* src = tensor ? kin : qin;

    // ---- stage cos/sin (8 rows x 64): first 128 threads ----
    if (tid < 128) {
        int r  = tid >> 4;
        int c4 = (tid & 15) << 2;
        size_t gofs = ((size_t)(b * SSS + s0 + r)) * DD + c4;
        *(float4*)&cs[r * XS_STRIDE + c4] = *(const float4*)(cosp + gofs);
        *(float4*)&ss[r * XS_STRIDE + c4] = *(const float4*)(sinp + gofs);
    }
    // ---- stage x (128 rows x 64), coalesced per 8-row head chunk ----
    #pragma unroll
    for (int it = 0; it < 8; ++it) {
        int lin = it * 256 + tid;
        int rl  = lin >> 4;
        int c4  = (lin & 15) << 2;
        int h   = rl >> 3, ds = rl & 7;
        size_t gofs = (((size_t)(b * 16 + h)) * SSS + s0 + ds) * DD + c4;
        *(float4*)&xs[rl * XS_STRIDE + c4] = *(const float4*)(src + gofs);
    }
    __syncthreads();

    // ---- A1 fragments for this warp's tile (rows [16*warp, 16*warp+16)) ----
    const int tb = warp * 16;
    uint32_t Ahi[4][4], Alo[4][4];
    {
        const float* x0 = &xs[(tb + g) * XS_STRIDE];
        const float* x1 = &xs[(tb + g + 8) * XS_STRIDE];
        #pragma unroll
        for (int kt = 0; kt < 4; ++kt) {
            int c0 = kt * 16 + 2 * t4;
            float2 p00 = *(const float2*)(x0 + c0);
            float2 p01 = *(const float2*)(x0 + c0 + 8);
            float2 p10 = *(const float2*)(x1 + c0);
            float2 p11 = *(const float2*)(x1 + c0 + 8);
            split_bf16x2(p00.x, p00.y, Ahi[kt][0], Alo[kt][0]);
            split_bf16x2(p10.x, p10.y, Ahi[kt][1], Alo[kt][1]);
            split_bf16x2(p01.x, p01.y, Ahi[kt][2], Alo[kt][2]);
            split_bf16x2(p11.x, p11.y, Ahi[kt][3], Alo[kt][3]);
        }
    }

    // ---- GEMM1: Y = X * Q^T (3-term bf16 split) ----
    float C[8][4];
    #pragma unroll
    for (int nt = 0; nt < 8; ++nt)
        #pragma unroll
        for (int e = 0; e < 4; ++e) C[nt][e] = 0.0f;

    #pragma unroll
    for (int nt = 0; nt < 8; ++nt) {
        #pragma unroll
        for (int kt = 0; kt < 4; ++kt) {
            uint4 bb = g_B1[(kt*8 + nt)*32 + lane];
            MMA_BF16(C[nt], Ahi[kt][0], Ahi[kt][1], Ahi[kt][2], Ahi[kt][3], bb.x, bb.y);
            MMA_BF16(C[nt], Alo[kt][0], Alo[kt][1], Alo[kt][2], Alo[kt][3], bb.x, bb.y);
            MMA_BF16(C[nt], Ahi[kt][0], Ahi[kt][1], Ahi[kt][2], Ahi[kt][3], bb.z, bb.w);
        }
    }

    // ---- rope: rows g and g+8 share s -> same cos/sin row ----
    {
        const float* cr = &cs[g * XS_STRIDE];
        const float* sr = &ss[g * XS_STRIDE];
        #pragma unroll
        for (int nt = 0; nt < 4; ++nt) {
            int c = 8*nt + 2*t4;
            float2 cl = *(const float2*)(cr + c);
            float2 ch = *(const float2*)(cr + c + 32);
            float2 sl = *(const float2*)(sr + c);
            float2 sh = *(const float2*)(sr + c + 32);
            #pragma unroll
            for (int e = 0; e < 4; ++e) {
                float cle = (e & 1) ? cl.y : cl.x;
                float che = (e & 1) ? ch.y : ch.x;
                float sle = (e & 1) ? sl.y : sl.x;
                float she = (e & 1) ? sh.y : sh.x;
                float ylo = C[nt][e], yhi = C[nt+4][e];
                C[nt][e]   = ylo*cle - yhi*sle;
                C[nt+4][e] = yhi*che + ylo*she;
            }
        }
    }

    // ---- Z (C fragments) -> A2 fragments ----
    #pragma unroll
    for (int kt = 0; kt < 4; ++kt) {
        split_bf16x2(C[2*kt][0],   C[2*kt][1],   Ahi[kt][0], Alo[kt][0]);
        split_bf16x2(C[2*kt][2],   C[2*kt][3],   Ahi[kt][1], Alo[kt][1]);
        split_bf16x2(C[2*kt+1][0], C[2*kt+1][1], Ahi[kt][2], Alo[kt][2]);
        split_bf16x2(C[2*kt+1][2], C[2*kt+1][3], Ahi[kt][3], Alo[kt][3]);
    }

    // ---- GEMM2: O = Z * Q ----
    #pragma unroll
    for (int nt = 0; nt < 8; ++nt)
        #pragma unroll
        for (int e = 0; e < 4; ++e) C[nt][e] = 0.0f;

    #pragma unroll
    for (int nt = 0; nt < 8; ++nt) {
        #pragma unroll
        for (int kt = 0; kt < 4; ++kt) {
            uint4 bb = g_B2[(kt*8 + nt)*32 + lane];
            MMA_BF16(C[nt], Ahi[kt][0], Ahi[kt][1], Ahi[kt][2], Ahi[kt][3], bb.x, bb.y);
            MMA_BF16(C[nt], Alo[kt][0], Alo[kt][1], Alo[kt][2], Alo[kt][3], bb.x, bb.y);
            MMA_BF16(C[nt], Ahi[kt][0], Ahi[kt][1], Ahi[kt][2], Ahi[kt][3], bb.z, bb.w);
        }
    }

    // ---- store: fragments -> smem (reuse xs), then coalesced flush ----
    __syncthreads();   // all warps done reading xs
    {
        float* o0 = &xs[(tb + g) * XS_STRIDE];
        float* o1 = &xs[(tb + g + 8) * XS_STRIDE];
        #pragma unroll
        for (int nt = 0; nt < 8; ++nt) {
            int c = 8*nt + 2*t4;
            float2 v0; v0.x = C[nt][0]; v0.y = C[nt][1];
            float2 v1; v1.x = C[nt][2]; v1.y = C[nt][3];
            *(float2*)(o0 + c) = v0;
            *(float2*)(o1 + c) = v1;
        }
    }
    __syncthreads();

    const size_t obase = (size_t)tensor * NROWS_Q * DD;
    #pragma unroll
    for (int it = 0; it < 8; ++it) {
        int lin = it * 256 + tid;
        int rl  = lin >> 4;
        int c4  = (lin & 15) << 2;
        int h   = rl >> 3, ds = rl & 7;
        size_t gofs = obase + (((size_t)(b * 16 + h)) * SSS + s0 + ds) * DD + c4;
        *(float4*)(out + gofs) = *(const float4*)&xs[rl * XS_STRIDE + c4];
    }
}

extern "C" void kernel_launch(void* const* d_in, const int* in_sizes, int n_in,
                              void* d_out, int out_size) {
    const float* q    = (const float*)d_in[0];
    const float* k    = (const float*)d_in[1];
    const float* cosp = (const float*)d_in[2];
    const float* sinp = (const float*)d_in[3];
    const float* vs   = (const float*)d_in[4];
    float* out = (float*)d_out;

    build_q_kernel<<<1, 256>>>(vs);
    rnrope_mma_kernel<<<NROWS_T / 128, 256>>>(q, k, cosp, sinp, out);
}

// round 5
// speedup vs baseline: 1.1444x; 1.1444x over previous
#include <cuda_runtime.h>
#include <cuda_fp16.h>
#include <cstdint>

// Shapes fixed by dataset: q/k (4,16,4096,64) f32, cos/sin (4,4096,64) f32, vs (32,64) f32
#define DD 64
#define SSS 4096
#define NROWS_Q (4*16*4096)    // 262144
#define NROWS_T (2*NROWS_Q)    // 524288
#define NREFL 32

// mma-ready packed fp16 B fragments (hi precision only), uint2 = {b0, b1}
// GEMM1: B1[k=j][n=i] = Q[i][j]   (Y = X * Q^T)
// GEMM2: B2[k=i][n=j] = Q[i][j]   (O = Z * Q)
__device__ uint2 g_B1[1024];
__device__ uint2 g_B2[1024];

// ---------------- Kernel A: build Q (Householder scan) + pack mma fragments ----------------
__global__ void build_q_kernel(const float* __restrict__ vs) {
    __shared__ float Qs[DD*DD];
    __shared__ float vsh[DD];
    __shared__ float wpart[4][DD];
    __shared__ float coefs[NREFL];
    const int t = threadIdx.x;          // 256 threads
    const int j = t & 63;
    const int p = t >> 6;

    for (int i = p*16; i < p*16 + 16; ++i)
        Qs[i*DD + j] = (i == j) ? 1.0f : 0.0f;

    if (t < NREFL) {
        float s = 0.0f;
        for (int c = 0; c < DD; ++c) { float v = vs[t*DD + c]; s += v*v; }
        coefs[t] = 2.0f / (s + 1e-8f);
    }
    __syncthreads();

    for (int r = 0; r < NREFL; ++r) {
        if (t < DD) vsh[t] = vs[r*DD + t];
        __syncthreads();
        float w = 0.0f;
        #pragma unroll
        for (int i = 0; i < 16; ++i) {
            int ii = p*16 + i;
            w += vsh[ii] * Qs[ii*DD + j];
        }
        wpart[p][j] = w;
        __syncthreads();
        float wj = wpart[0][j] + wpart[1][j] + wpart[2][j] + wpart[3][j];
        float cw = coefs[r] * wj;
        #pragma unroll
        for (int i = 0; i < 16; ++i) {
            int ii = p*16 + i;
            Qs[ii*DD + j] -= vsh[ii] * cw;
        }
        __syncthreads();
    }

    // pack B fragments (fp16) for both GEMMs
    for (int slot = t; slot < 1024; slot += 256) {
        int lane = slot & 31, frag = slot >> 5;
        int kt = frag >> 3, nt = frag & 7;
        int g = lane >> 2, t4 = lane & 3;
        int n  = 8*nt + g;
        int k0 = 16*kt + 2*t4;

        // ---- B1 (element at (k,n) = Q[n][k]) ----
        {
            __half2 h0 = __floats2half2_rn(Qs[n*DD + k0],     Qs[n*DD + k0 + 1]);
            __half2 h1 = __floats2half2_rn(Qs[n*DD + k0 + 8], Qs[n*DD + k0 + 9]);
            g_B1[slot] = make_uint2(*(uint32_t*)&h0, *(uint32_t*)&h1);
        }
        // ---- B2 (element at (k,n) = Q[k][n]) ----
        {
            __half2 h0 = __floats2half2_rn(Qs[k0*DD + n],     Qs[(k0+1)*DD + n]);
            __half2 h1 = __floats2half2_rn(Qs[(k0+8)*DD + n], Qs[(k0+9)*DD + n]);
            g_B2[slot] = make_uint2(*(uint32_t*)&h0, *(uint32_t*)&h1);
        }
    }
}

// ---------------- helpers ----------------
// 2-term fp16 split of a float pair: hi = f16(a,b); lo = f16(a-hi.x, b-hi.y)
__device__ __forceinline__ void split_f16x2(float a, float b, uint32_t& hi, uint32_t& lo) {
    __half2 h = __floats2half2_rn(a, b);
    float2 hf = __half22float2(h);
    __half2 l = __floats2half2_rn(a - hf.x, b - hf.y);
    hi = *(uint32_t*)&h;
    lo = *(uint32_t*)&l;
}

#define MMA_F16(c, a0, a1, a2, a3, b0, b1)                                         \
    asm volatile("mma.sync.aligned.m16n8k16.row.col.f32.f16.f16.f32 "              \
                 "{%0,%1,%2,%3}, {%4,%5,%6,%7}, {%8,%9}, {%0,%1,%2,%3};"           \
                 : "+f"(c[0]), "+f"(c[1]), "+f"(c[2]), "+f"(c[3])                   \
                 : "r"(a0), "r"(a1), "r"(a2), "r"(a3), "r"(b0), "r"(b1))

// ---------------- Kernel B ----------------
// Block = 256 threads (8 warps). Block covers ONE (tensor, b, s-chunk of 8) across ALL 16 heads:
// 128 rows, local row rl = h*8 + ds. Each warp handles ONE 16-row M-tile (2 heads).
// cos/sin tile is 8 rows, shared by all heads and both fragment row-halves.
#define XS_STRIDE 68
__global__ void __launch_bounds__(256, 2) rnrope_mma_kernel(
    const float* __restrict__ qin, const float* __restrict__ kin,
    const float* __restrict__ cosp, const float* __restrict__ sinp,
    float* __restrict__ out)
{
    __shared__ float xs[128 * XS_STRIDE];   // x tile; reused for out tile
    __shared__ float cs[8 * XS_STRIDE];
    __shared__ float ss[8 * XS_STRIDE];

    const int tid  = threadIdx.x;
    const int warp = tid >> 5;
    const int lane = tid & 31;
    const int g    = lane >> 2;
    const int t4   = lane & 3;

    const int bid    = blockIdx.x;          // 4096 blocks
    const int tensor = bid >> 11;           // 0 = q, 1 = k
    const int b      = (bid >> 9) & 3;
    const int s0     = (bid & 511) << 3;
    const float* src = tensor ? kin : qin;

    // ---- stage cos/sin (8 rows x 64): first 128 threads ----
    if (tid < 128) {
        int r  = tid >> 4;
        int c4 = (tid & 15) << 2;
        size_t gofs = ((size_t)(b * SSS + s0 + r)) * DD + c4;
        *(float4*)&cs[r * XS_STRIDE + c4] = *(const float4*)(cosp + gofs);
        *(float4*)&ss[r * XS_STRIDE + c4] = *(const float4*)(sinp + gofs);
    }
    // ---- stage x (128 rows x 64), coalesced per 8-row head chunk ----
    #pragma unroll
    for (int it = 0; it < 8; ++it) {
        int lin = it * 256 + tid;
        int rl  = lin >> 4;
        int c4  = (lin & 15) << 2;
        int h   = rl >> 3, ds = rl & 7;
        size_t gofs = (((size_t)(b * 16 + h)) * SSS + s0 + ds) * DD + c4;
        *(float4*)&xs[rl * XS_STRIDE + c4] = *(const float4*)(src + gofs);
    }
    __syncthreads();

    // ---- A1 fragments for this warp's tile (rows [16*warp, 16*warp+16)) ----
    const int tb = warp * 16;
    uint32_t Ahi[4][4], Alo[4][4];
    {
        const float* x0 = &xs[(tb + g) * XS_STRIDE];
        const float* x1 = &xs[(tb + g + 8) * XS_STRIDE];
        #pragma unroll
        for (int kt = 0; kt < 4; ++kt) {
            int c0 = kt * 16 + 2 * t4;
            float2 p00 = *(const float2*)(x0 + c0);
            float2 p01 = *(const float2*)(x0 + c0 + 8);
            float2 p10 = *(const float2*)(x1 + c0);
            float2 p11 = *(const float2*)(x1 + c0 + 8);
            split_f16x2(p00.x, p00.y, Ahi[kt][0], Alo[kt][0]);
            split_f16x2(p10.x, p10.y, Ahi[kt][1], Alo[kt][1]);
            split_f16x2(p01.x, p01.y, Ahi[kt][2], Alo[kt][2]);
            split_f16x2(p11.x, p11.y, Ahi[kt][3], Alo[kt][3]);
        }
    }

    // ---- GEMM1: Y = X * Q^T (2-term fp16 split) ----
    float C[8][4];
    #pragma unroll
    for (int nt = 0; nt < 8; ++nt)
        #pragma unroll
        for (int e = 0; e < 4; ++e) C[nt][e] = 0.0f;

    #pragma unroll
    for (int nt = 0; nt < 8; ++nt) {
        #pragma unroll
        for (int kt = 0; kt < 4; ++kt) {
            uint2 bb = g_B1[(kt*8 + nt)*32 + lane];
            MMA_F16(C[nt], Ahi[kt][0], Ahi[kt][1], Ahi[kt][2], Ahi[kt][3], bb.x, bb.y);
            MMA_F16(C[nt], Alo[kt][0], Alo[kt][1], Alo[kt][2], Alo[kt][3], bb.x, bb.y);
        }
    }

    // ---- rope: rows g and g+8 share s -> same cos/sin row ----
    {
        const float* cr = &cs[g * XS_STRIDE];
        const float* sr = &ss[g * XS_STRIDE];
        #pragma unroll
        for (int nt = 0; nt < 4; ++nt) {
            int c = 8*nt + 2*t4;
            float2 cl = *(const float2*)(cr + c);
            float2 ch = *(const float2*)(cr + c + 32);
            float2 sl = *(const float2*)(sr + c);
            float2 sh = *(const float2*)(sr + c + 32);
            #pragma unroll
            for (int e = 0; e < 4; ++e) {
                float cle = (e & 1) ? cl.y : cl.x;
                float che = (e & 1) ? ch.y : ch.x;
                float sle = (e & 1) ? sl.y : sl.x;
                float she = (e & 1) ? sh.y : sh.x;
                float ylo = C[nt][e], yhi = C[nt+4][e];
                C[nt][e]   = ylo*cle - yhi*sle;
                C[nt+4][e] = yhi*che + ylo*she;
            }
        }
    }

    // ---- Z (C fragments) -> A2 fragments ----
    #pragma unroll
    for (int kt = 0; kt < 4; ++kt) {
        split_f16x2(C[2*kt][0],   C[2*kt][1],   Ahi[kt][0], Alo[kt][0]);
        split_f16x2(C[2*kt][2],   C[2*kt][3],   Ahi[kt][1], Alo[kt][1]);
        split_f16x2(C[2*kt+1][0], C[2*kt+1][1], Ahi[kt][2], Alo[kt][2]);
        split_f16x2(C[2*kt+1][2], C[2*kt+1][3], Ahi[kt][3], Alo[kt][3]);
    }

    // ---- GEMM2: O = Z * Q ----
    #pragma unroll
    for (int nt = 0; nt < 8; ++nt)
        #pragma unroll
        for (int e = 0; e < 4; ++e) C[nt][e] = 0.0f;

    #pragma unroll
    for (int nt = 0; nt < 8; ++nt) {
        #pragma unroll
        for (int kt = 0; kt < 4; ++kt) {
            uint2 bb = g_B2[(kt*8 + nt)*32 + lane];
            MMA_F16(C[nt], Ahi[kt][0], Ahi[kt][1], Ahi[kt][2], Ahi[kt][3], bb.x, bb.y);
            MMA_F16(C[nt], Alo[kt][0], Alo[kt][1], Alo[kt][2], Alo[kt][3], bb.x, bb.y);
        }
    }

    // ---- store: fragments -> smem (reuse xs), then coalesced flush ----
    __syncthreads();   // all warps done reading xs
    {
        float* o0 = &xs[(tb + g) * XS_STRIDE];
        float* o1 = &xs[(tb + g + 8) * XS_STRIDE];
        #pragma unroll
        for (int nt = 0; nt < 8; ++nt) {
            int c = 8*nt + 2*t4;
            float2 v0; v0.x = C[nt][0]; v0.y = C[nt][1];
            float2 v1; v1.x = C[nt][2]; v1.y = C[nt][3];
            *(float2*)(o0 + c) = v0;
            *(float2*)(o1 + c) = v1;
        }
    }
    __syncthreads();

    const size_t obase = (size_t)tensor * NROWS_Q * DD;
    #pragma unroll
    for (int it = 0; it < 8; ++it) {
        int lin = it * 256 + tid;
        int rl  = lin >> 4;
        int c4  = (lin & 15) << 2;
        int h   = rl >> 3, ds = rl & 7;
        size_t gofs = obase + (((size_t)(b * 16 + h)) * SSS + s0 + ds) * DD + c4;
        *(float4*)(out + gofs) = *(const float4*)&xs[rl * XS_STRIDE + c4];
    }
}

extern "C" void kernel_launch(void* const* d_in, const int* in_sizes, int n_in,
                              void* d_out, int out_size) {
    const float* q    = (const float*)d_in[0];
    const float* k    = (const float*)d_in[1];
    const float* cosp = (const float*)d_in[2];
    const float* sinp = (const float*)d_in[3];
    const float* vs   = (const float*)d_in[4];
    float* out = (float*)d_out;

    build_q_kernel<<<1, 256>>>(vs);
    rnrope_mma_kernel<<<NROWS_T / 128, 256>>>(q, k, cosp, sinp, out);
}

// round 6
// speedup vs baseline: 1.3663x; 1.1939x over previous
#include <cuda_runtime.h>
#include <cuda_fp16.h>
#include <cstdint>

// Shapes fixed by dataset: q/k (4,16,4096,64) f32, cos/sin (4,4096,64) f32, vs (32,64) f32
#define DD 64
#define SSS 4096
#define NROWS_Q (4*16*4096)    // 262144
#define NROWS_T (2*NROWS_Q)    // 524288
#define NREFL 32

// mma-ready packed fp16 B fragments, uint2 = {b0, b1}
// GEMM1: B1[k=j][n=i] = Q[i][j]   (Y = X * Q^T)
// GEMM2: B2[k=i][n=j] = Q[i][j]   (O = Z * Q)
__device__ uint2 g_B1[1024];
__device__ uint2 g_B2[1024];

// ---------------- Kernel A: build Q, barrier-free column-owner scan ----------------
// Column j of Q is only ever read/written through column j in the scan:
//   w_j = sum_i v_i Q[i][j];  Q[i][j] -= v_i * (c * w_j)
// So each column evolves independently. 128 threads: thread owns 32 rows of one
// column in REGISTERS; partner thread (lane^16, same warp) owns the other 32 rows.
// One shfl_xor per reflection, no __syncthreads in the loop.
__global__ void build_q_kernel(const float* __restrict__ vs) {
    __shared__ float vsh[NREFL*DD];     // all reflection vectors, 8KB
    __shared__ float coefs[NREFL];
    __shared__ float Qs[DD*DD];
    const int tid  = threadIdx.x;       // 128
    const int lane = tid & 31;
    const int warp = tid >> 5;

    for (int i = tid; i < NREFL*DD; i += 128) vsh[i] = vs[i];
    __syncthreads();
    if (tid < NREFL) {
        float s = 0.0f;
        #pragma unroll
        for (int c = 0; c < DD; ++c) { float v = vsh[tid*DD + c]; s += v*v; }
        coefs[tid] = 2.0f / (s + 1e-8f);
    }
    __syncthreads();

    const int col = (warp << 4) | (lane & 15);   // 0..63
    const int seg = lane >> 4;                   // 0: rows 0-31, 1: rows 32-63
    float qc[32];
    #pragma unroll
    for (int i = 0; i < 32; ++i) qc[i] = (seg*32 + i == col) ? 1.0f : 0.0f;

    for (int r = 0; r < NREFL; ++r) {
        const float* v = &vsh[r*DD + seg*32];
        float w0 = 0.0f, w1 = 0.0f, w2 = 0.0f, w3 = 0.0f;
        #pragma unroll
        for (int i = 0; i < 32; i += 4) {
            w0 += v[i]   * qc[i];
            w1 += v[i+1] * qc[i+1];
            w2 += v[i+2] * qc[i+2];
            w3 += v[i+3] * qc[i+3];
        }
        float w = (w0 + w1) + (w2 + w3);
        w += __shfl_xor_sync(0xffffffffu, w, 16);
        float cw = coefs[r] * w;
        #pragma unroll
        for (int i = 0; i < 32; ++i) qc[i] -= v[i] * cw;
    }

    #pragma unroll
    for (int i = 0; i < 32; ++i) Qs[(seg*32 + i)*DD + col] = qc[i];
    __syncthreads();

    // pack B fragments (fp16) for both GEMMs
    for (int slot = tid; slot < 1024; slot += 128) {
        int l = slot & 31, frag = slot >> 5;
        int kt = frag >> 3, nt = frag & 7;
        int g = l >> 2, t4 = l & 3;
        int n  = 8*nt + g;
        int k0 = 16*kt + 2*t4;

        // B1 (element at (k,n) = Q[n][k])
        {
            __half2 h0 = __floats2half2_rn(Qs[n*DD + k0],     Qs[n*DD + k0 + 1]);
            __half2 h1 = __floats2half2_rn(Qs[n*DD + k0 + 8], Qs[n*DD + k0 + 9]);
            g_B1[slot] = make_uint2(*(uint32_t*)&h0, *(uint32_t*)&h1);
        }
        // B2 (element at (k,n) = Q[k][n])
        {
            __half2 h0 = __floats2half2_rn(Qs[k0*DD + n],     Qs[(k0+1)*DD + n]);
            __half2 h1 = __floats2half2_rn(Qs[(k0+8)*DD + n], Qs[(k0+9)*DD + n]);
            g_B2[slot] = make_uint2(*(uint32_t*)&h0, *(uint32_t*)&h1);
        }
    }
}

// ---------------- helpers ----------------
__device__ __forceinline__ void split_f16x2(float a, float b, uint32_t& hi, uint32_t& lo) {
    __half2 h = __floats2half2_rn(a, b);
    float2 hf = __half22float2(h);
    __half2 l = __floats2half2_rn(a - hf.x, b - hf.y);
    hi = *(uint32_t*)&h;
    lo = *(uint32_t*)&l;
}

#define MMA_F16(c, a0, a1, a2, a3, b0, b1)                                         \
    asm volatile("mma.sync.aligned.m16n8k16.row.col.f32.f16.f16.f32 "              \
                 "{%0,%1,%2,%3}, {%4,%5,%6,%7}, {%8,%9}, {%0,%1,%2,%3};"           \
                 : "+f"(c[0]), "+f"(c[1]), "+f"(c[2]), "+f"(c[3])                   \
                 : "r"(a0), "r"(a1), "r"(a2), "r"(a3), "r"(b0), "r"(b1))

// ---------------- Kernel B ----------------
// Block = 128 threads (4 warps), covers ONE (tensor, b, s-chunk of 8) across ALL 16 heads:
// 128 rows, rl = h*8 + ds. Each warp handles TWO 16-row M-tiles (B fragments amortized 2x).
#define XS_STRIDE 68
__global__ void __launch_bounds__(128, 3) rnrope_mma_kernel(
    const float* __restrict__ qin, const float* __restrict__ kin,
    const float* __restrict__ cosp, const float* __restrict__ sinp,
    float* __restrict__ out)
{
    __shared__ float xs[128 * XS_STRIDE];   // x tile; reused for out tile
    __shared__ float cs[8 * XS_STRIDE];
    __shared__ float ss[8 * XS_STRIDE];

    const int tid  = threadIdx.x;
    const int warp = tid >> 5;
    const int lane = tid & 31;
    const int g    = lane >> 2;
    const int t4   = lane & 3;

    const int bid    = blockIdx.x;          // 4096 blocks
    const int tensor = bid >> 11;           // 0 = q, 1 = k
    const int b      = (bid >> 9) & 3;
    const int s0     = (bid & 511) << 3;
    const float* src = tensor ? kin : qin;

    // ---- stage cos/sin (8 rows x 64) ----
    {
        int r  = tid >> 4;
        int c4 = (tid & 15) << 2;
        size_t gofs = ((size_t)(b * SSS + s0 + r)) * DD + c4;
        *(float4*)&cs[r * XS_STRIDE + c4] = *(const float4*)(cosp + gofs);
        *(float4*)&ss[r * XS_STRIDE + c4] = *(const float4*)(sinp + gofs);
    }
    // ---- stage x (128 rows x 64), coalesced per 8-row head chunk ----
    #pragma unroll
    for (int it = 0; it < 16; ++it) {
        int lin = it * 128 + tid;
        int rl  = lin >> 4;
        int c4  = (lin & 15) << 2;
        int h   = rl >> 3, ds = rl & 7;
        size_t gofs = (((size_t)(b * 16 + h)) * SSS + s0 + ds) * DD + c4;
        *(float4*)&xs[rl * XS_STRIDE + c4] = *(const float4*)(src + gofs);
    }
    __syncthreads();

    // ---- A1 fragments for the warp's two tiles ----
    uint32_t Ahi[2][4][4], Alo[2][4][4];
    #pragma unroll
    for (int tt = 0; tt < 2; ++tt) {
        int tb = (warp * 2 + tt) * 16;
        const float* x0 = &xs[(tb + g) * XS_STRIDE];
        const float* x1 = &xs[(tb + g + 8) * XS_STRIDE];
        #pragma unroll
        for (int kt = 0; kt < 4; ++kt) {
            int c0 = kt * 16 + 2 * t4;
            float2 p00 = *(const float2*)(x0 + c0);
            float2 p01 = *(const float2*)(x0 + c0 + 8);
            float2 p10 = *(const float2*)(x1 + c0);
            float2 p11 = *(const float2*)(x1 + c0 + 8);
            split_f16x2(p00.x, p00.y, Ahi[tt][kt][0], Alo[tt][kt][0]);
            split_f16x2(p10.x, p10.y, Ahi[tt][kt][1], Alo[tt][kt][1]);
            split_f16x2(p01.x, p01.y, Ahi[tt][kt][2], Alo[tt][kt][2]);
            split_f16x2(p11.x, p11.y, Ahi[tt][kt][3], Alo[tt][kt][3]);
        }
    }

    // ---- GEMM1: Y = X * Q^T (2-term fp16), B fragment shared by both tiles ----
    float C0[8][4], C1[8][4];
    #pragma unroll
    for (int nt = 0; nt < 8; ++nt)
        #pragma unroll
        for (int e = 0; e < 4; ++e) { C0[nt][e] = 0.0f; C1[nt][e] = 0.0f; }

    #pragma unroll
    for (int nt = 0; nt < 8; ++nt) {
        #pragma unroll
        for (int kt = 0; kt < 4; ++kt) {
            uint2 bb = g_B1[(kt*8 + nt)*32 + lane];
            MMA_F16(C0[nt], Ahi[0][kt][0], Ahi[0][kt][1], Ahi[0][kt][2], Ahi[0][kt][3], bb.x, bb.y);
            MMA_F16(C0[nt], Alo[0][kt][0], Alo[0][kt][1], Alo[0][kt][2], Alo[0][kt][3], bb.x, bb.y);
            MMA_F16(C1[nt], Ahi[1][kt][0], Ahi[1][kt][1], Ahi[1][kt][2], Ahi[1][kt][3], bb.x, bb.y);
            MMA_F16(C1[nt], Alo[1][kt][0], Alo[1][kt][1], Alo[1][kt][2], Alo[1][kt][3], bb.x, bb.y);
        }
    }

    // ---- rope: rows g and g+8 share s -> same cos/sin; both tiles share too ----
    {
        const float* cr = &cs[g * XS_STRIDE];
        const float* sr = &ss[g * XS_STRIDE];
        #pragma unroll
        for (int nt = 0; nt < 4; ++nt) {
            int c = 8*nt + 2*t4;
            float2 cl = *(const float2*)(cr + c);
            float2 ch = *(const float2*)(cr + c + 32);
            float2 sl = *(const float2*)(sr + c);
            float2 sh = *(const float2*)(sr + c + 32);
            #pragma unroll
            for (int e = 0; e < 4; ++e) {
                float cle = (e & 1) ? cl.y : cl.x;
                float che = (e & 1) ? ch.y : ch.x;
                float sle = (e & 1) ? sl.y : sl.x;
                float she = (e & 1) ? sh.y : sh.x;
                float ylo0 = C0[nt][e], yhi0 = C0[nt+4][e];
                C0[nt][e]   = ylo0*cle - yhi0*sle;
                C0[nt+4][e] = yhi0*che + ylo0*she;
                float ylo1 = C1[nt][e], yhi1 = C1[nt+4][e];
                C1[nt][e]   = ylo1*cle - yhi1*sle;
                C1[nt+4][e] = yhi1*che + ylo1*she;
            }
        }
    }

    // ---- Z -> A2 fragments (reuse A register arrays) ----
    #pragma unroll
    for (int kt = 0; kt < 4; ++kt) {
        split_f16x2(C0[2*kt][0],   C0[2*kt][1],   Ahi[0][kt][0], Alo[0][kt][0]);
        split_f16x2(C0[2*kt][2],   C0[2*kt][3],   Ahi[0][kt][1], Alo[0][kt][1]);
        split_f16x2(C0[2*kt+1][0], C0[2*kt+1][1], Ahi[0][kt][2], Alo[0][kt][2]);
        split_f16x2(C0[2*kt+1][2], C0[2*kt+1][3], Ahi[0][kt][3], Alo[0][kt][3]);
        split_f16x2(C1[2*kt][0],   C1[2*kt][1],   Ahi[1][kt][0], Alo[1][kt][0]);
        split_f16x2(C1[2*kt][2],   C1[2*kt][3],   Ahi[1][kt][1], Alo[1][kt][1]);
        split_f16x2(C1[2*kt+1][0], C1[2*kt+1][1], Ahi[1][kt][2], Alo[1][kt][2]);
        split_f16x2(C1[2*kt+1][2], C1[2*kt+1][3], Ahi[1][kt][3], Alo[1][kt][3]);
    }

    // ---- GEMM2: O = Z * Q ----
    #pragma unroll
    for (int nt = 0; nt < 8; ++nt)
        #pragma unroll
        for (int e = 0; e < 4; ++e) { C0[nt][e] = 0.0f; C1[nt][e] = 0.0f; }

    #pragma unroll
    for (int nt = 0; nt < 8; ++nt) {
        #pragma unroll
        for (int kt = 0; kt < 4; ++kt) {
            uint2 bb = g_B2[(kt*8 + nt)*32 + lane];
            MMA_F16(C0[nt], Ahi[0][kt][0], Ahi[0][kt][1], Ahi[0][kt][2], Ahi[0][kt][3], bb.x, bb.y);
            MMA_F16(C0[nt], Alo[0][kt][0], Alo[0][kt][1], Alo[0][kt][2], Alo[0][kt][3], bb.x, bb.y);
            MMA_F16(C1[nt], Ahi[1][kt][0], Ahi[1][kt][1], Ahi[1][kt][2], Ahi[1][kt][3], bb.x, bb.y);
            MMA_F16(C1[nt], Alo[1][kt][0], Alo[1][kt][1], Alo[1][kt][2], Alo[1][kt][3], bb.x, bb.y);
        }
    }

    // ---- store: fragments -> smem (reuse xs), then coalesced flush ----
    __syncthreads();   // all warps done reading xs
    #pragma unroll
    for (int tt = 0; tt < 2; ++tt) {
        int tb = (warp * 2 + tt) * 16;
        float* o0 = &xs[(tb + g) * XS_STRIDE];
        float* o1 = &xs[(tb + g + 8) * XS_STRIDE];
        #pragma unroll
        for (int nt = 0; nt < 8; ++nt) {
            int c = 8*nt + 2*t4;
            float2 v0, v1;
            if (tt == 0) { v0.x = C0[nt][0]; v0.y = C0[nt][1]; v1.x = C0[nt][2]; v1.y = C0[nt][3]; }
            else         { v0.x = C1[nt][0]; v0.y = C1[nt][1]; v1.x = C1[nt][2]; v1.y = C1[nt][3]; }
            *(float2*)(o0 + c) = v0;
            *(float2*)(o1 + c) = v1;
        }
    }
    __syncthreads();

    const size_t obase = (size_t)tensor * NROWS_Q * DD;
    #pragma unroll
    for (int it = 0; it < 16; ++it) {
        int lin = it * 128 + tid;
        int rl  = lin >> 4;
        int c4  = (lin & 15) << 2;
        int h   = rl >> 3, ds = rl & 7;
        size_t gofs = obase + (((size_t)(b * 16 + h)) * SSS + s0 + ds) * DD + c4;
        *(float4*)(out + gofs) = *(const float4*)&xs[rl * XS_STRIDE + c4];
    }
}

extern "C" void kernel_launch(void* const* d_in, const int* in_sizes, int n_in,
                              void* d_out, int out_size) {
    const float* q    = (const float*)d_in[0];
    const float* k    = (const float*)d_in[1];
    const float* cosp = (const float*)d_in[2];
    const float* sinp = (const float*)d_in[3];
    const float* vs   = (const float*)d_in[4];
    float* out = (float*)d_out;

    build_q_kernel<<<1, 128>>>(vs);
    rnrope_mma_kernel<<<NROWS_T / 128, 128>>>(q, k, cosp, sinp, out);
}

// round 7
// speedup vs baseline: 1.3704x; 1.0030x over previous
#include <cuda_runtime.h>
#include <cuda_fp16.h>
#include <cstdint>

// Shapes fixed by dataset: q/k (4,16,4096,64) f32, cos/sin (4,4096,64) f32, vs (32,64) f32
#define DD 64
#define SSS 4096
#define NROWS_Q (4*16*4096)    // 262144
#define NROWS_T (2*NROWS_Q)    // 524288
#define NREFL 32

// mma-ready packed fp16 B fragments, uint2 = {b0, b1}
// GEMM1: B1[k=j][n=i] = Q[i][j]   (Y = X * Q^T)
// GEMM2: B2[k=i][n=j] = Q[i][j]   (O = Z * Q)
__device__ uint2 g_B1[1024];
__device__ uint2 g_B2[1024];

// ---------------- cp.async helpers ----------------
__device__ __forceinline__ void cp_async16(uint32_t dst_smem, const void* src) {
    asm volatile("cp.async.cg.shared.global [%0], [%1], 16;" :: "r"(dst_smem), "l"(src));
}
__device__ __forceinline__ void cp_async_commit() {
    asm volatile("cp.async.commit_group;" ::: "memory");
}
__device__ __forceinline__ void cp_async_wait0() {
    asm volatile("cp.async.wait_group 0;" ::: "memory");
}

// ---------------- Kernel A: build Q, barrier-free column-owner scan ----------------
// Column j of Q evolves independently: w_j = v . Q[:,j]; Q[:,j] -= (c w_j) v.
// 128 threads: thread owns 32 rows of one column in registers; partner (lane^16)
// owns the other 32. One shfl per reflection, no __syncthreads in the loop.
__global__ void build_q_kernel(const float* __restrict__ vs) {
    __shared__ __align__(16) float vsh[NREFL*DD];     // 8KB
    __shared__ float coefs[NREFL];
    __shared__ float Qs[DD*DD];
    const int tid  = threadIdx.x;       // 128
    const int lane = tid & 31;
    const int warp = tid >> 5;

    for (int i = tid; i < NREFL*DD/4; i += 128)
        ((float4*)vsh)[i] = ((const float4*)vs)[i];
    __syncthreads();
    if (tid < NREFL) {
        float s = 0.0f;
        const float4* v4 = (const float4*)&vsh[tid*DD];
        #pragma unroll
        for (int c = 0; c < 16; ++c) {
            float4 v = v4[c];
            s += v.x*v.x + v.y*v.y + v.z*v.z + v.w*v.w;
        }
        coefs[tid] = 2.0f / (s + 1e-8f);
    }
    __syncthreads();

    const int col = (warp << 4) | (lane & 15);   // 0..63
    const int seg = lane >> 4;                   // 0: rows 0-31, 1: rows 32-63
    float qc[32];
    #pragma unroll
    for (int i = 0; i < 32; ++i) qc[i] = (seg*32 + i == col) ? 1.0f : 0.0f;

    for (int r = 0; r < NREFL; ++r) {
        const float4* v4 = (const float4*)&vsh[r*DD + seg*32];
        float4 vv[8];
        #pragma unroll
        for (int i = 0; i < 8; ++i) vv[i] = v4[i];
        float w0 = 0.f, w1 = 0.f, w2 = 0.f, w3 = 0.f;
        #pragma unroll
        for (int i = 0; i < 8; ++i) {
            w0 += vv[i].x * qc[4*i];
            w1 += vv[i].y * qc[4*i+1];
            w2 += vv[i].z * qc[4*i+2];
            w3 += vv[i].w * qc[4*i+3];
        }
        float w = (w0 + w1) + (w2 + w3);
        w += __shfl_xor_sync(0xffffffffu, w, 16);
        float cw = coefs[r] * w;
        #pragma unroll
        for (int i = 0; i < 8; ++i) {
            qc[4*i]   -= vv[i].x * cw;
            qc[4*i+1] -= vv[i].y * cw;
            qc[4*i+2] -= vv[i].z * cw;
            qc[4*i+3] -= vv[i].w * cw;
        }
    }

    #pragma unroll
    for (int i = 0; i < 32; ++i) Qs[(seg*32 + i)*DD + col] = qc[i];
    __syncthreads();

    // pack B fragments (fp16) for both GEMMs
    for (int slot = tid; slot < 1024; slot += 128) {
        int l = slot & 31, frag = slot >> 5;
        int kt = frag >> 3, nt = frag & 7;
        int g = l >> 2, t4 = l & 3;
        int n  = 8*nt + g;
        int k0 = 16*kt + 2*t4;

        // B1 (element at (k,n) = Q[n][k])
        {
            __half2 h0 = __floats2half2_rn(Qs[n*DD + k0],     Qs[n*DD + k0 + 1]);
            __half2 h1 = __floats2half2_rn(Qs[n*DD + k0 + 8], Qs[n*DD + k0 + 9]);
            g_B1[slot] = make_uint2(*(uint32_t*)&h0, *(uint32_t*)&h1);
        }
        // B2 (element at (k,n) = Q[k][n])
        {
            __half2 h0 = __floats2half2_rn(Qs[k0*DD + n],     Qs[(k0+1)*DD + n]);
            __half2 h1 = __floats2half2_rn(Qs[(k0+8)*DD + n], Qs[(k0+9)*DD + n]);
            g_B2[slot] = make_uint2(*(uint32_t*)&h0, *(uint32_t*)&h1);
        }
    }
}

// ---------------- helpers ----------------
__device__ __forceinline__ void split_f16x2(float a, float b, uint32_t& hi, uint32_t& lo) {
    __half2 h = __floats2half2_rn(a, b);
    float2 hf = __half22float2(h);
    __half2 l = __floats2half2_rn(a - hf.x, b - hf.y);
    hi = *(uint32_t*)&h;
    lo = *(uint32_t*)&l;
}

#define MMA_F16(c, a0, a1, a2, a3, b0, b1)                                         \
    asm volatile("mma.sync.aligned.m16n8k16.row.col.f32.f16.f16.f32 "              \
                 "{%0,%1,%2,%3}, {%4,%5,%6,%7}, {%8,%9}, {%0,%1,%2,%3};"           \
                 : "+f"(c[0]), "+f"(c[1]), "+f"(c[2]), "+f"(c[3])                   \
                 : "r"(a0), "r"(a1), "r"(a2), "r"(a3), "r"(b0), "r"(b1))

// ---------------- Kernel B ----------------
// Block = 128 threads (4 warps), covers ONE (tensor, b, s-chunk of 8) across ALL 16 heads:
// 128 rows, rl = h*8 + ds. Each warp handles TWO 16-row M-tiles (B fragments amortized 2x).
#define XS_STRIDE 68
__global__ void __launch_bounds__(128, 3) rnrope_mma_kernel(
    const float* __restrict__ qin, const float* __restrict__ kin,
    const float* __restrict__ cosp, const float* __restrict__ sinp,
    float* __restrict__ out)
{
    __shared__ __align__(16) float xs[128 * XS_STRIDE];   // x tile; reused for out tile
    __shared__ __align__(16) float cs[8 * XS_STRIDE];
    __shared__ __align__(16) float ss[8 * XS_STRIDE];

    const int tid  = threadIdx.x;
    const int warp = tid >> 5;
    const int lane = tid & 31;
    const int g    = lane >> 2;
    const int t4   = lane & 3;

    const int bid    = blockIdx.x;          // 4096 blocks
    const int tensor = bid >> 11;           // 0 = q, 1 = k
    const int b      = (bid >> 9) & 3;
    const int s0     = (bid & 511) << 3;
    const float* src = tensor ? kin : qin;

    // ---- stage cos/sin (8 rows x 64) via cp.async ----
    {
        int r  = tid >> 4;
        int c4 = (tid & 15) << 2;
        size_t gofs = ((size_t)(b * SSS + s0 + r)) * DD + c4;
        uint32_t cdst = (uint32_t)__cvta_generic_to_shared(&cs[r * XS_STRIDE + c4]);
        uint32_t sdst = (uint32_t)__cvta_generic_to_shared(&ss[r * XS_STRIDE + c4]);
        cp_async16(cdst, cosp + gofs);
        cp_async16(sdst, sinp + gofs);
    }
    // ---- stage x (128 rows x 64) via cp.async, coalesced per 8-row head chunk ----
    #pragma unroll
    for (int it = 0; it < 16; ++it) {
        int lin = it * 128 + tid;
        int rl  = lin >> 4;
        int c4  = (lin & 15) << 2;
        int h   = rl >> 3, ds = rl & 7;
        size_t gofs = (((size_t)(b * 16 + h)) * SSS + s0 + ds) * DD + c4;
        uint32_t dst = (uint32_t)__cvta_generic_to_shared(&xs[rl * XS_STRIDE + c4]);
        cp_async16(dst, src + gofs);
    }
    cp_async_commit();
    cp_async_wait0();
    __syncthreads();

    // ---- A1 fragments for the warp's two tiles ----
    uint32_t Ahi[2][4][4], Alo[2][4][4];
    #pragma unroll
    for (int tt = 0; tt < 2; ++tt) {
        int tb = (warp * 2 + tt) * 16;
        const float* x0 = &xs[(tb + g) * XS_STRIDE];
        const float* x1 = &xs[(tb + g + 8) * XS_STRIDE];
        #pragma unroll
        for (int kt = 0; kt < 4; ++kt) {
            int c0 = kt * 16 + 2 * t4;
            float2 p00 = *(const float2*)(x0 + c0);
            float2 p01 = *(const float2*)(x0 + c0 + 8);
            float2 p10 = *(const float2*)(x1 + c0);
            float2 p11 = *(const float2*)(x1 + c0 + 8);
            split_f16x2(p00.x, p00.y, Ahi[tt][kt][0], Alo[tt][kt][0]);
            split_f16x2(p10.x, p10.y, Ahi[tt][kt][1], Alo[tt][kt][1]);
            split_f16x2(p01.x, p01.y, Ahi[tt][kt][2], Alo[tt][kt][2]);
            split_f16x2(p11.x, p11.y, Ahi[tt][kt][3], Alo[tt][kt][3]);
        }
    }

    // ---- GEMM1: Y = X * Q^T (2-term fp16), kt-outer: consecutive mma hit different C ----
    float C0[8][4], C1[8][4];
    #pragma unroll
    for (int nt = 0; nt < 8; ++nt)
        #pragma unroll
        for (int e = 0; e < 4; ++e) { C0[nt][e] = 0.0f; C1[nt][e] = 0.0f; }

    #pragma unroll
    for (int kt = 0; kt < 4; ++kt) {
        #pragma unroll
        for (int nt = 0; nt < 8; ++nt) {
            uint2 bb = g_B1[(kt*8 + nt)*32 + lane];
            MMA_F16(C0[nt], Ahi[0][kt][0], Ahi[0][kt][1], Ahi[0][kt][2], Ahi[0][kt][3], bb.x, bb.y);
            MMA_F16(C0[nt], Alo[0][kt][0], Alo[0][kt][1], Alo[0][kt][2], Alo[0][kt][3], bb.x, bb.y);
            MMA_F16(C1[nt], Ahi[1][kt][0], Ahi[1][kt][1], Ahi[1][kt][2], Ahi[1][kt][3], bb.x, bb.y);
            MMA_F16(C1[nt], Alo[1][kt][0], Alo[1][kt][1], Alo[1][kt][2], Alo[1][kt][3], bb.x, bb.y);
        }
    }

    // ---- rope: rows g and g+8 share s -> same cos/sin; both tiles share too ----
    {
        const float* cr = &cs[g * XS_STRIDE];
        const float* sr = &ss[g * XS_STRIDE];
        #pragma unroll
        for (int nt = 0; nt < 4; ++nt) {
            int c = 8*nt + 2*t4;
            float2 cl = *(const float2*)(cr + c);
            float2 ch = *(const float2*)(cr + c + 32);
            float2 sl = *(const float2*)(sr + c);
            float2 sh = *(const float2*)(sr + c + 32);
            #pragma unroll
            for (int e = 0; e < 4; ++e) {
                float cle = (e & 1) ? cl.y : cl.x;
                float che = (e & 1) ? ch.y : ch.x;
                float sle = (e & 1) ? sl.y : sl.x;
                float she = (e & 1) ? sh.y : sh.x;
                float ylo0 = C0[nt][e], yhi0 = C0[nt+4][e];
                C0[nt][e]   = ylo0*cle - yhi0*sle;
                C0[nt+4][e] = yhi0*che + ylo0*she;
                float ylo1 = C1[nt][e], yhi1 = C1[nt+4][e];
                C1[nt][e]   = ylo1*cle - yhi1*sle;
                C1[nt+4][e] = yhi1*che + ylo1*she;
            }
        }
    }

    // ---- Z -> A2 fragments (reuse A register arrays) ----
    #pragma unroll
    for (int kt = 0; kt < 4; ++kt) {
        split_f16x2(C0[2*kt][0],   C0[2*kt][1],   Ahi[0][kt][0], Alo[0][kt][0]);
        split_f16x2(C0[2*kt][2],   C0[2*kt][3],   Ahi[0][kt][1], Alo[0][kt][1]);
        split_f16x2(C0[2*kt+1][0], C0[2*kt+1][1], Ahi[0][kt][2], Alo[0][kt][2]);
        split_f16x2(C0[2*kt+1][2], C0[2*kt+1][3], Ahi[0][kt][3], Alo[0][kt][3]);
        split_f16x2(C1[2*kt][0],   C1[2*kt][1],   Ahi[1][kt][0], Alo[1][kt][0]);
        split_f16x2(C1[2*kt][2],   C1[2*kt][3],   Ahi[1][kt][1], Alo[1][kt][1]);
        split_f16x2(C1[2*kt+1][0], C1[2*kt+1][1], Ahi[1][kt][2], Alo[1][kt][2]);
        split_f16x2(C1[2*kt+1][2], C1[2*kt+1][3], Ahi[1][kt][3], Alo[1][kt][3]);
    }

    // ---- GEMM2: O = Z * Q (kt-outer) ----
    #pragma unroll
    for (int nt = 0; nt < 8; ++nt)
        #pragma unroll
        for (int e = 0; e < 4; ++e) { C0[nt][e] = 0.0f; C1[nt][e] = 0.0f; }

    #pragma unroll
    for (int kt = 0; kt < 4; ++kt) {
        #pragma unroll
        for (int nt = 0; nt < 8; ++nt) {
            uint2 bb = g_B2[(kt*8 + nt)*32 + lane];
            MMA_F16(C0[nt], Ahi[0][kt][0], Ahi[0][kt][1], Ahi[0][kt][2], Ahi[0][kt][3], bb.x, bb.y);
            MMA_F16(C0[nt], Alo[0][kt][0], Alo[0][kt][1], Alo[0][kt][2], Alo[0][kt][3], bb.x, bb.y);
            MMA_F16(C1[nt], Ahi[1][kt][0], Ahi[1][kt][1], Ahi[1][kt][2], Ahi[1][kt][3], bb.x, bb.y);
            MMA_F16(C1[nt], Alo[1][kt][0], Alo[1][kt][1], Alo[1][kt][2], Alo[1][kt][3], bb.x, bb.y);
        }
    }

    // ---- store: fragments -> smem (reuse xs), then coalesced flush ----
    __syncthreads();   // all warps done reading xs
    #pragma unroll
    for (int tt = 0; tt < 2; ++tt) {
        int tb = (warp * 2 + tt) * 16;
        float* o0 = &xs[(tb + g) * XS_STRIDE];
        float* o1 = &xs[(tb + g + 8) * XS_STRIDE];
        #pragma unroll
        for (int nt = 0; nt < 8; ++nt) {
            int c = 8*nt + 2*t4;
            float2 v0, v1;
            if (tt == 0) { v0.x = C0[nt][0]; v0.y = C0[nt][1]; v1.x = C0[nt][2]; v1.y = C0[nt][3]; }
            else         { v0.x = C1[nt][0]; v0.y = C1[nt][1]; v1.x = C1[nt][2]; v1.y = C1[nt][3]; }
            *(float2*)(o0 + c) = v0;
            *(float2*)(o1 + c) = v1;
        }
    }
    __syncthreads();

    const size_t obase = (size_t)tensor * NROWS_Q * DD;
    #pragma unroll
    for (int it = 0; it < 16; ++it) {
        int lin = it * 128 + tid;
        int rl  = lin >> 4;
        int c4  = (lin & 15) << 2;
        int h   = rl >> 3, ds = rl & 7;
        size_t gofs = obase + (((size_t)(b * 16 + h)) * SSS + s0 + ds) * DD + c4;
        *(float4*)(out + gofs) = *(const float4*)&xs[rl * XS_STRIDE + c4];
    }
}

extern "C" void kernel_launch(void* const* d_in, const int* in_sizes, int n_in,
                              void* d_out, int out_size) {
    const float* q    = (const float*)d_in[0];
    const float* k    = (const float*)d_in[1];
    const float* cosp = (const float*)d_in[2];
    const float* sinp = (const float*)d_in[3];
    const float* vs   = (const float*)d_in[4];
    float* out = (float*)d_out;

    build_q_kernel<<<1, 128>>>(vs);
    rnrope_mma_kernel<<<NROWS_T / 128, 128>>>(q, k, cosp, sinp, out);
}

// round 8
// speedup vs baseline: 1.4740x; 1.0756x over previous
#include <cuda_runtime.h>
#include <cuda_fp16.h>
#include <cstdint>

// Shapes fixed by dataset: q/k (4,16,4096,64) f32, cos/sin (4,4096,64) f32, vs (32,64) f32
#define DD 64
#define SSS 4096
#define NROWS_Q (4*16*4096)    // 262144
#define NROWS_T (2*NROWS_Q)    // 524288
#define NREFL 32

// mma-ready packed fp16 B fragments, uint2 = {b0, b1}
// GEMM1: B1[k=j][n=i] = Q[i][j]   (Y = X * Q^T)
// GEMM2: B2[k=i][n=j] = Q[i][j]   (O = Z * Q)
__device__ uint2 g_B1[1024];
__device__ uint2 g_B2[1024];

// ---------------- Kernel A: build Q, barrier-free column-owner scan ----------------
// Column j of Q evolves independently: w_j = v . Q[:,j]; Q[:,j] -= (c w_j) v.
// First 128 threads: thread owns 32 rows of one column in registers; partner
// (lane^16) owns the other 32. One shfl per reflection, no __syncthreads in loop.
// All 256 threads participate in the fragment packing.
__global__ void build_q_kernel(const float* __restrict__ vs) {
    __shared__ __align__(16) float vsh[NREFL*DD];     // 8KB
    __shared__ float coefs[NREFL];
    __shared__ float Qs[DD*DD];
    const int tid  = threadIdx.x;       // 256
    const int lane = tid & 31;
    const int warp = tid >> 5;

    for (int i = tid; i < NREFL*DD/4; i += 256)
        ((float4*)vsh)[i] = ((const float4*)vs)[i];
    __syncthreads();
    if (tid < NREFL) {
        float s = 0.0f;
        const float4* v4 = (const float4*)&vsh[tid*DD];
        #pragma unroll
        for (int c = 0; c < 16; ++c) {
            float4 v = v4[c];
            s += v.x*v.x + v.y*v.y + v.z*v.z + v.w*v.w;
        }
        coefs[tid] = 2.0f / (s + 1e-8f);
    }
    __syncthreads();

    if (warp < 4) {
        const int col = (warp << 4) | (lane & 15);   // 0..63
        const int seg = lane >> 4;                   // 0: rows 0-31, 1: rows 32-63
        float qc[32];
        #pragma unroll
        for (int i = 0; i < 32; ++i) qc[i] = (seg*32 + i == col) ? 1.0f : 0.0f;

        for (int r = 0; r < NREFL; ++r) {
            const float4* v4 = (const float4*)&vsh[r*DD + seg*32];
            float4 vv[8];
            #pragma unroll
            for (int i = 0; i < 8; ++i) vv[i] = v4[i];
            float w0 = 0.f, w1 = 0.f, w2 = 0.f, w3 = 0.f;
            #pragma unroll
            for (int i = 0; i < 8; ++i) {
                w0 += vv[i].x * qc[4*i];
                w1 += vv[i].y * qc[4*i+1];
                w2 += vv[i].z * qc[4*i+2];
                w3 += vv[i].w * qc[4*i+3];
            }
            float w = (w0 + w1) + (w2 + w3);
            w += __shfl_xor_sync(0xffffffffu, w, 16);
            float cw = coefs[r] * w;
            #pragma unroll
            for (int i = 0; i < 8; ++i) {
                qc[4*i]   -= vv[i].x * cw;
                qc[4*i+1] -= vv[i].y * cw;
                qc[4*i+2] -= vv[i].z * cw;
                qc[4*i+3] -= vv[i].w * cw;
            }
        }

        #pragma unroll
        for (int i = 0; i < 32; ++i) Qs[(seg*32 + i)*DD + col] = qc[i];
    }
    __syncthreads();

    // pack B fragments (fp16) for both GEMMs — all 256 threads
    for (int slot = tid; slot < 1024; slot += 256) {
        int l = slot & 31, frag = slot >> 5;
        int kt = frag >> 3, nt = frag & 7;
        int g = l >> 2, t4 = l & 3;
        int n  = 8*nt + g;
        int k0 = 16*kt + 2*t4;

        // B1 (element at (k,n) = Q[n][k])
        {
            __half2 h0 = __floats2half2_rn(Qs[n*DD + k0],     Qs[n*DD + k0 + 1]);
            __half2 h1 = __floats2half2_rn(Qs[n*DD + k0 + 8], Qs[n*DD + k0 + 9]);
            g_B1[slot] = make_uint2(*(uint32_t*)&h0, *(uint32_t*)&h1);
        }
        // B2 (element at (k,n) = Q[k][n])
        {
            __half2 h0 = __floats2half2_rn(Qs[k0*DD + n],     Qs[(k0+1)*DD + n]);
            __half2 h1 = __floats2half2_rn(Qs[(k0+8)*DD + n], Qs[(k0+9)*DD + n]);
            g_B2[slot] = make_uint2(*(uint32_t*)&h0, *(uint32_t*)&h1);
        }
    }
}

// ---------------- helpers ----------------
__device__ __forceinline__ void split_f16x2(float a, float b, uint32_t& hi, uint32_t& lo) {
    __half2 h = __floats2half2_rn(a, b);
    float2 hf = __half22float2(h);
    __half2 l = __floats2half2_rn(a - hf.x, b - hf.y);
    hi = *(uint32_t*)&h;
    lo = *(uint32_t*)&l;
}

#define MMA_F16(c, a0, a1, a2, a3, b0, b1)                                         \
    asm volatile("mma.sync.aligned.m16n8k16.row.col.f32.f16.f16.f32 "              \
                 "{%0,%1,%2,%3}, {%4,%5,%6,%7}, {%8,%9}, {%0,%1,%2,%3};"           \
                 : "+f"(c[0]), "+f"(c[1]), "+f"(c[2]), "+f"(c[3])                   \
                 : "r"(a0), "r"(a1), "r"(a2), "r"(a3), "r"(b0), "r"(b1))

// ---------------- Kernel B ----------------
// Block = 128 threads (4 warps), covers ONE (tensor, b, s-chunk of 8) across ALL 16 heads:
// 128 rows, rl = h*8 + ds. Each warp handles TWO 16-row M-tiles (B fragments amortized 2x).
// MMA emission: per kt, hi-pass over all 16 accumulators, then lo-pass -> reuse
// distance 16 between MMAs touching the same accumulator (covers HMMA latency).
#define XS_STRIDE 68
__global__ void __launch_bounds__(128, 3) rnrope_mma_kernel(
    const float* __restrict__ qin, const float* __restrict__ kin,
    const float* __restrict__ cosp, const float* __restrict__ sinp,
    float* __restrict__ out)
{
    __shared__ __align__(16) float xs[128 * XS_STRIDE];   // x tile; reused for out tile
    __shared__ __align__(16) float cs[8 * XS_STRIDE];
    __shared__ __align__(16) float ss[8 * XS_STRIDE];

    const int tid  = threadIdx.x;
    const int warp = tid >> 5;
    const int lane = tid & 31;
    const int g    = lane >> 2;
    const int t4   = lane & 3;

    const int bid    = blockIdx.x;          // 4096 blocks
    const int tensor = bid >> 11;           // 0 = q, 1 = k
    const int b      = (bid >> 9) & 3;
    const int s0     = (bid & 511) << 3;
    const float* src = tensor ? kin : qin;

    // ---- stage cos/sin (8 rows x 64) ----
    {
        int r  = tid >> 4;
        int c4 = (tid & 15) << 2;
        size_t gofs = ((size_t)(b * SSS + s0 + r)) * DD + c4;
        *(float4*)&cs[r * XS_STRIDE + c4] = *(const float4*)(cosp + gofs);
        *(float4*)&ss[r * XS_STRIDE + c4] = *(const float4*)(sinp + gofs);
    }
    // ---- stage x (128 rows x 64), coalesced per 8-row head chunk ----
    #pragma unroll
    for (int it = 0; it < 16; ++it) {
        int lin = it * 128 + tid;
        int rl  = lin >> 4;
        int c4  = (lin & 15) << 2;
        int h   = rl >> 3, ds = rl & 7;
        size_t gofs = (((size_t)(b * 16 + h)) * SSS + s0 + ds) * DD + c4;
        *(float4*)&xs[rl * XS_STRIDE + c4] = *(const float4*)(src + gofs);
    }
    __syncthreads();

    // ---- A1 fragments for the warp's two tiles ----
    uint32_t Ahi[2][4][4], Alo[2][4][4];
    #pragma unroll
    for (int tt = 0; tt < 2; ++tt) {
        int tb = (warp * 2 + tt) * 16;
        const float* x0 = &xs[(tb + g) * XS_STRIDE];
        const float* x1 = &xs[(tb + g + 8) * XS_STRIDE];
        #pragma unroll
        for (int kt = 0; kt < 4; ++kt) {
            int c0 = kt * 16 + 2 * t4;
            float2 p00 = *(const float2*)(x0 + c0);
            float2 p01 = *(const float2*)(x0 + c0 + 8);
            float2 p10 = *(const float2*)(x1 + c0);
            float2 p11 = *(const float2*)(x1 + c0 + 8);
            split_f16x2(p00.x, p00.y, Ahi[tt][kt][0], Alo[tt][kt][0]);
            split_f16x2(p10.x, p10.y, Ahi[tt][kt][1], Alo[tt][kt][1]);
            split_f16x2(p01.x, p01.y, Ahi[tt][kt][2], Alo[tt][kt][2]);
            split_f16x2(p11.x, p11.y, Ahi[tt][kt][3], Alo[tt][kt][3]);
        }
    }

    // ---- GEMM1: Y = X * Q^T (2-term fp16) ----
    float C0[8][4], C1[8][4];
    #pragma unroll
    for (int nt = 0; nt < 8; ++nt)
        #pragma unroll
        for (int e = 0; e < 4; ++e) { C0[nt][e] = 0.0f; C1[nt][e] = 0.0f; }

    #pragma unroll
    for (int kt = 0; kt < 4; ++kt) {
        uint2 bb[8];
        #pragma unroll
        for (int nt = 0; nt < 8; ++nt) bb[nt] = g_B1[(kt*8 + nt)*32 + lane];
        // hi-pass: 16 independent accumulators back-to-back
        #pragma unroll
        for (int nt = 0; nt < 8; ++nt) {
            MMA_F16(C0[nt], Ahi[0][kt][0], Ahi[0][kt][1], Ahi[0][kt][2], Ahi[0][kt][3], bb[nt].x, bb[nt].y);
            MMA_F16(C1[nt], Ahi[1][kt][0], Ahi[1][kt][1], Ahi[1][kt][2], Ahi[1][kt][3], bb[nt].x, bb[nt].y);
        }
        // lo-pass
        #pragma unroll
        for (int nt = 0; nt < 8; ++nt) {
            MMA_F16(C0[nt], Alo[0][kt][0], Alo[0][kt][1], Alo[0][kt][2], Alo[0][kt][3], bb[nt].x, bb[nt].y);
            MMA_F16(C1[nt], Alo[1][kt][0], Alo[1][kt][1], Alo[1][kt][2], Alo[1][kt][3], bb[nt].x, bb[nt].y);
        }
    }

    // ---- rope: rows g and g+8 share s -> same cos/sin; both tiles share too ----
    {
        const float* cr = &cs[g * XS_STRIDE];
        const float* sr = &ss[g * XS_STRIDE];
        #pragma unroll
        for (int nt = 0; nt < 4; ++nt) {
            int c = 8*nt + 2*t4;
            float2 cl = *(const float2*)(cr + c);
            float2 ch = *(const float2*)(cr + c + 32);
            float2 sl = *(const float2*)(sr + c);
            float2 sh = *(const float2*)(sr + c + 32);
            #pragma unroll
            for (int e = 0; e < 4; ++e) {
                float cle = (e & 1) ? cl.y : cl.x;
                float che = (e & 1) ? ch.y : ch.x;
                float sle = (e & 1) ? sl.y : sl.x;
                float she = (e & 1) ? sh.y : sh.x;
                float ylo0 = C0[nt][e], yhi0 = C0[nt+4][e];
                C0[nt][e]   = ylo0*cle - yhi0*sle;
                C0[nt+4][e] = yhi0*che + ylo0*she;
                float ylo1 = C1[nt][e], yhi1 = C1[nt+4][e];
                C1[nt][e]   = ylo1*cle - yhi1*sle;
                C1[nt+4][e] = yhi1*che + ylo1*she;
            }
        }
    }

    // ---- Z -> A2 fragments (reuse A register arrays) ----
    #pragma unroll
    for (int kt = 0; kt < 4; ++kt) {
        split_f16x2(C0[2*kt][0],   C0[2*kt][1],   Ahi[0][kt][0], Alo[0][kt][0]);
        split_f16x2(C0[2*kt][2],   C0[2*kt][3],   Ahi[0][kt][1], Alo[0][kt][1]);
        split_f16x2(C0[2*kt+1][0], C0[2*kt+1][1], Ahi[0][kt][2], Alo[0][kt][2]);
        split_f16x2(C0[2*kt+1][2], C0[2*kt+1][3], Ahi[0][kt][3], Alo[0][kt][3]);
        split_f16x2(C1[2*kt][0],   C1[2*kt][1],   Ahi[1][kt][0], Alo[1][kt][0]);
        split_f16x2(C1[2*kt][2],   C1[2*kt][3],   Ahi[1][kt][1], Alo[1][kt][1]);
        split_f16x2(C1[2*kt+1][0], C1[2*kt+1][1], Ahi[1][kt][2], Alo[1][kt][2]);
        split_f16x2(C1[2*kt+1][2], C1[2*kt+1][3], Ahi[1][kt][3], Alo[1][kt][3]);
    }

    // ---- GEMM2: O = Z * Q ----
    #pragma unroll
    for (int nt = 0; nt < 8; ++nt)
        #pragma unroll
        for (int e = 0; e < 4; ++e) { C0[nt][e] = 0.0f; C1[nt][e] = 0.0f; }

    #pragma unroll
    for (int kt = 0; kt < 4; ++kt) {
        uint2 bb[8];
        #pragma unroll
        for (int nt = 0; nt < 8; ++nt) bb[nt] = g_B2[(kt*8 + nt)*32 + lane];
        #pragma unroll
        for (int nt = 0; nt < 8; ++nt) {
            MMA_F16(C0[nt], Ahi[0][kt][0], Ahi[0][kt][1], Ahi[0][kt][2], Ahi[0][kt][3], bb[nt].x, bb[nt].y);
            MMA_F16(C1[nt], Ahi[1][kt][0], Ahi[1][kt][1], Ahi[1][kt][2], Ahi[1][kt][3], bb[nt].x, bb[nt].y);
        }
        #pragma unroll
        for (int nt = 0; nt < 8; ++nt) {
            MMA_F16(C0[nt], Alo[0][kt][0], Alo[0][kt][1], Alo[0][kt][2], Alo[0][kt][3], bb[nt].x, bb[nt].y);
            MMA_F16(C1[nt], Alo[1][kt][0], Alo[1][kt][1], Alo[1][kt][2], Alo[1][kt][3], bb[nt].x, bb[nt].y);
        }
    }

    // ---- store: fragments -> smem (reuse xs), then coalesced flush ----
    __syncthreads();   // all warps done reading xs
    #pragma unroll
    for (int tt = 0; tt < 2; ++tt) {
        int tb = (warp * 2 + tt) * 16;
        float* o0 = &xs[(tb + g) * XS_STRIDE];
        float* o1 = &xs[(tb + g + 8) * XS_STRIDE];
        #pragma unroll
        for (int nt = 0; nt < 8; ++nt) {
            int c = 8*nt + 2*t4;
            float2 v0, v1;
            if (tt == 0) { v0.x = C0[nt][0]; v0.y = C0[nt][1]; v1.x = C0[nt][2]; v1.y = C0[nt][3]; }
            else         { v0.x = C1[nt][0]; v0.y = C1[nt][1]; v1.x = C1[nt][2]; v1.y = C1[nt][3]; }
            *(float2*)(o0 + c) = v0;
            *(float2*)(o1 + c) = v1;
        }
    }
    __syncthreads();

    const size_t obase = (size_t)tensor * NROWS_Q * DD;
    #pragma unroll
    for (int it = 0; it < 16; ++it) {
        int lin = it * 128 + tid;
        int rl  = lin >> 4;
        int c4  = (lin & 15) << 2;
        int h   = rl >> 3, ds = rl & 7;
        size_t gofs = obase + (((size_t)(b * 16 + h)) * SSS + s0 + ds) * DD + c4;
        *(float4*)(out + gofs) = *(const float4*)&xs[rl * XS_STRIDE + c4];
    }
}

extern "C" void kernel_launch(void* const* d_in, const int* in_sizes, int n_in,
                              void* d_out, int out_size) {
    const float* q    = (const float*)d_in[0];
    const float* k    = (const float*)d_in[1];
    const float* cosp = (const float*)d_in[2];
    const float* sinp = (const float*)d_in[3];
    const float* vs   = (const float*)d_in[4];
    float* out = (float*)d_out;

    build_q_kernel<<<1, 256>>>(vs);
    rnrope_mma_kernel<<<NROWS_T / 128, 128>>>(q, k, cosp, sinp, out);
}